// round 15
// baseline (speedup 1.0000x reference)
#include <cuda_runtime.h>
#include <cuda_fp16.h>
#include <cstdint>

// Problem constants
#define D_MODEL 1024
#define S_LEN   2048
#define NH      16
#define HDIM    64
#define NBATCH  2
#define NTOK    (NBATCH * S_LEN)   // 4096
#define DD      (D_MODEL * D_MODEL)

// Scratch (static __device__ globals — allocation-free per harness rules)
__device__ __half g_Xh [NTOK * D_MODEL];
__device__ __half g_Wh [4 * DD];            // Wq, Wk, Wv, Wo (fp16)
__device__ __half g_Qh [NTOK * D_MODEL];    // pre-scaled by log2e/8
__device__ __half g_Kh [NTOK * D_MODEL];
__device__ __half g_Vh [NTOK * D_MODEL];
__device__ __half g_AOh[NTOK * D_MODEL];

// ---------------------------------------------------------------------------
// Helpers (legacy tensor-core path — tcgen05 rejected by sm_100 PTX target).
// ---------------------------------------------------------------------------
__device__ __forceinline__ uint32_t f2h2(float lo, float hi) {
    __half2 h = __floats2half2_rn(lo, hi);
    return *(uint32_t*)&h;
}
__device__ __forceinline__ uint32_t smem_addr_u32(const void* p) {
    return (uint32_t)__cvta_generic_to_shared(p);
}
__device__ __forceinline__ float ex2(float x) {
    float y; asm("ex2.approx.f32 %0, %1;" : "=f"(y) : "f"(x)); return y;
}
__device__ __forceinline__ void mma_f16(float* d, const uint32_t* a, const uint32_t* b) {
    asm volatile(
        "mma.sync.aligned.m16n8k16.row.col.f32.f16.f16.f32 "
        "{%0,%1,%2,%3}, {%4,%5,%6,%7}, {%8,%9}, {%0,%1,%2,%3};"
        : "+f"(d[0]), "+f"(d[1]), "+f"(d[2]), "+f"(d[3])
        : "r"(a[0]), "r"(a[1]), "r"(a[2]), "r"(a[3]), "r"(b[0]), "r"(b[1]));
}
__device__ __forceinline__ void ldsm4(uint32_t& r0, uint32_t& r1,
                                      uint32_t& r2, uint32_t& r3, uint32_t addr) {
    asm volatile("ldmatrix.sync.aligned.m8n8.x4.shared.b16 {%0,%1,%2,%3}, [%4];"
                 : "=r"(r0), "=r"(r1), "=r"(r2), "=r"(r3) : "r"(addr));
}
__device__ __forceinline__ void ldsm4t(uint32_t& r0, uint32_t& r1,
                                       uint32_t& r2, uint32_t& r3, uint32_t addr) {
    asm volatile("ldmatrix.sync.aligned.m8n8.x4.trans.shared.b16 {%0,%1,%2,%3}, [%4];"
                 : "=r"(r0), "=r"(r1), "=r"(r2), "=r"(r3) : "r"(addr));
}
__device__ __forceinline__ void cp16(uint32_t dst, const void* src) {
    asm volatile("cp.async.cg.shared.global [%0], [%1], 16;" :: "r"(dst), "l"(src));
}
__device__ __forceinline__ void cp_commit() {
    asm volatile("cp.async.commit_group;" ::: "memory");
}
__device__ __forceinline__ void cp_wait2() {
    asm volatile("cp.async.wait_group 2;" ::: "memory");
}
__device__ __forceinline__ void cp_wait1() {
    asm volatile("cp.async.wait_group 1;" ::: "memory");
}
__device__ __forceinline__ void cp_wait0() {
    asm volatile("cp.async.wait_group 0;" ::: "memory");
}

// ===========================================================================
// fp32 -> fp16 conversion (X + 4 weight matrices).
// ===========================================================================
__global__ void convert_fp16(const float* __restrict__ X,
                             const float* __restrict__ Wq, const float* __restrict__ Wk,
                             const float* __restrict__ Wv, const float* __restrict__ Wo)
{
    const float* src; __half* dst; uint32_t n4;
    switch (blockIdx.z) {
        case 0:  src = X;  dst = g_Xh;          n4 = NTOK * D_MODEL / 4; break;
        case 1:  src = Wq; dst = g_Wh;          n4 = DD / 4; break;
        case 2:  src = Wk; dst = g_Wh + DD;     n4 = DD / 4; break;
        case 3:  src = Wv; dst = g_Wh + 2 * DD; n4 = DD / 4; break;
        default: src = Wo; dst = g_Wh + 3 * DD; n4 = DD / 4; break;
    }
    for (uint32_t i = blockIdx.x * blockDim.x + threadIdx.x; i < n4;
         i += gridDim.x * blockDim.x) {
        float4 v = ((const float4*)src)[i];
        uint2 w = {f2h2(v.x, v.y), f2h2(v.z, v.w)};
        ((uint2*)dst)[i] = w;
    }
}

// ===========================================================================
// fp16 tensor-core GEMM with cp.async 4-stage pipeline.
// ===========================================================================
#define ROWB 80
#define STG_BYTES (256 * ROWB)
#define GEMM_SMEM_BYTES (4 * STG_BYTES)         // 81920 B

template <bool HALF_OUT, typename OutT>
__device__ __forceinline__ void gemm_body(
    const __half* __restrict__ A, const __half* __restrict__ B,
    const float* __restrict__ bias, OutT* __restrict__ C,
    int bM, int bN, float scale, void* smv)
{
    const int tid  = threadIdx.x;
    const int lane = tid & 31;
    const int wid  = tid >> 5;
    const int g    = lane >> 2;
    const int t    = lane & 3;
    const int wm   = (wid >> 2) * 64;
    const int wn   = (wid & 3) * 32;

    const uint32_t smu = smem_addr_u32(smv);
    const uint32_t aLane = smu + (lane & 15) * ROWB + ((lane >> 4) << 4);
    const uint32_t bLane = aLane + 128 * ROWB;

    const int ch = tid & 3;
    const int rr = tid >> 2;
    const __half* sA0 = A + (size_t)(bM + rr) * D_MODEL + ch * 8;
    const __half* sA1 = sA0 + (size_t)64 * D_MODEL;
    const __half* sB0 = B + (size_t)(bN + rr) * D_MODEL + ch * 8;
    const __half* sB1 = sB0 + (size_t)64 * D_MODEL;
    const uint32_t dA0 = rr * ROWB + ch * 16;
    const uint32_t dA1 = dA0 + 64 * ROWB;
    const uint32_t dB0 = dA0 + 128 * ROWB;
    const uint32_t dB1 = dB0 + 64 * ROWB;

    float acc[16][4];
    #pragma unroll
    for (int i = 0; i < 16; i++)
        #pragma unroll
        for (int j = 0; j < 4; j++) acc[i][j] = 0.0f;

    // Prologue: stages 0,1,2 in flight.
    #pragma unroll
    for (int s = 0; s < 3; s++) {
        const uint32_t sb = smu + s * STG_BYTES;
        const int kt = s * 32;
        cp16(sb + dA0, sA0 + kt);
        cp16(sb + dA1, sA1 + kt);
        cp16(sb + dB0, sB0 + kt);
        cp16(sb + dB1, sB1 + kt);
        cp_commit();
    }

    for (int s = 0; s < 32; s++) {
        if (s < 30) cp_wait2(); else cp_wait0();   // stage s landed
        __syncthreads();

        if (s + 3 < 32) {
            const uint32_t sb = smu + ((s + 3) & 3) * STG_BYTES;
            const int kt = (s + 3) * 32;
            cp16(sb + dA0, sA0 + kt);
            cp16(sb + dA1, sA1 + kt);
            cp16(sb + dB0, sB0 + kt);
            cp16(sb + dB1, sB1 + kt);
            cp_commit();
        }

        const uint32_t bufByte = (uint32_t)(s & 3) * STG_BYTES;
        #pragma unroll
        for (int ks = 0; ks < 2; ks++) {
            const uint32_t kByte = bufByte + ks * 32;
            uint32_t af[4][4];
            #pragma unroll
            for (int i = 0; i < 4; i++)
                ldsm4(af[i][0], af[i][1], af[i][2], af[i][3],
                      aLane + kByte + (wm + i * 16) * ROWB);
            #pragma unroll
            for (int j = 0; j < 2; j++) {
                uint32_t m0, m1, m2, m3;
                ldsm4(m0, m1, m2, m3, bLane + kByte + (wn + j * 16) * ROWB);
                uint32_t b0[2] = {m0, m2}, b1[2] = {m1, m3};
                #pragma unroll
                for (int i = 0; i < 4; i++) {
                    mma_f16(acc[i * 4 + 2 * j],     af[i], b0);
                    mma_f16(acc[i * 4 + 2 * j + 1], af[i], b1);
                }
            }
        }
    }

    #pragma unroll
    for (int i = 0; i < 4; i++) {
        const int m0 = bM + wm + i * 16 + g;
        #pragma unroll
        for (int j = 0; j < 4; j++) {
            const int col = bN + wn + j * 8 + 2 * t;
            float2 bb = *(const float2*)(bias + col);
            float v00 = (acc[i * 4 + j][0] + bb.x) * scale;
            float v01 = (acc[i * 4 + j][1] + bb.y) * scale;
            float v10 = (acc[i * 4 + j][2] + bb.x) * scale;
            float v11 = (acc[i * 4 + j][3] + bb.y) * scale;
            if (HALF_OUT) {
                uint32_t* o = (uint32_t*)C;
                o[((size_t)m0 * D_MODEL + col) >> 1]       = f2h2(v00, v01);
                o[((size_t)(m0 + 8) * D_MODEL + col) >> 1] = f2h2(v10, v11);
            } else {
                float* o = (float*)C;
                *(float2*)(o + (size_t)m0 * D_MODEL + col)       = make_float2(v00, v01);
                *(float2*)(o + (size_t)(m0 + 8) * D_MODEL + col) = make_float2(v10, v11);
            }
        }
    }
}

// Fused QKV. Q is pre-scaled by log2e/8 so softmax runs in log2 domain.
#define QSCALE (0.125f * 1.44269504f)

__global__ __launch_bounds__(256, 2)
void gemm_qkv(const float* __restrict__ bq, const float* __restrict__ bk,
              const float* __restrict__ bv)
{
    extern __shared__ char smg[];
    const __half* B; const float* bias; __half* C; float scale;
    if (blockIdx.z == 0)      { B = g_Wh;          bias = bq; C = g_Qh; scale = QSCALE; }
    else if (blockIdx.z == 1) { B = g_Wh + DD;     bias = bk; C = g_Kh; scale = 1.0f; }
    else                      { B = g_Wh + 2 * DD; bias = bv; C = g_Vh; scale = 1.0f; }
    gemm_body<true>(g_Xh, B, bias, C, blockIdx.y * 128, blockIdx.x * 128, scale, smg);
}

__global__ __launch_bounds__(256, 2)
void gemm_out(const float* __restrict__ bo, float* __restrict__ out)
{
    extern __shared__ char smg[];
    gemm_body<false>(g_AOh, g_Wh + 3 * DD, bo, out,
                     blockIdx.y * 128, blockIdx.x * 128, 1.0f, smg);
}

// ===========================================================================
// fp16 causal flash attention v3:
//  - softmax in log2 domain (Q pre-scaled by log2e/8; ex2.approx)
//  - diagonal k-tiles skip warp-uniformly fully-masked mma blocks
//  - P in registers; V via ldmatrix.trans; cp.async double-buffered K/V
// ===========================================================================
#define QT 128
#define KT 64
#define PADW 36
#define KV_STG_B (2 * KT * PADW * 4)                    // 18432 B per stage
#define ATTN_SMEM_BYTES (QT * PADW * 4 + 2 * KV_STG_B)  // 55296 B

__global__ __launch_bounds__(256, 2)
void attn_mma()
{
    extern __shared__ uint32_t sma[];
    uint32_t* Qs = sma;
    uint32_t* St = sma + QT * PADW;

    const int tid  = threadIdx.x;
    const int lane = tid & 31;
    const int wid  = tid >> 5;
    const int g    = lane >> 2;
    const int t    = lane & 3;
    const int qt   = (int)(gridDim.x - 1) - (int)blockIdx.x;
    const int h    = blockIdx.y;
    const int n    = blockIdx.z;
    const int qb0  = qt * QT;
    const int row0 = wid * 16;
    const int rowMax = qb0 + row0 + 15;   // warp's last query row

    const uint32_t laneOfs = (((lane & 15) * PADW + ((lane >> 4) << 2)) << 2);
    const uint32_t qLane  = smem_addr_u32(Qs) + laneOfs + ((row0 * PADW) << 2);
    const uint32_t stBase = smem_addr_u32(St);

    const size_t headbase = ((size_t)n * S_LEN) * D_MODEL + h * HDIM;

    {
        const __half* Qg = g_Qh + headbase + (size_t)qb0 * D_MODEL;
        #pragma unroll
        for (int i = 0; i < 4; i++) {
            int idx = tid + i * 256;
            int r = idx >> 3, c8 = idx & 7;
            uint4 v = *(const uint4*)(Qg + (size_t)r * D_MODEL + c8 * 8);
            *(uint4*)(Qs + r * PADW + c8 * 4) = v;
        }
    }

    const int c8s = tid & 7;
    const int rKs = tid >> 3;
    const uint32_t dK0 = rKs * 144 + c8s * 16;
    const uint32_t dK1 = dK0 + 32 * 144;
    const uint32_t dV0 = dK0 + KT * 144;
    const uint32_t dV1 = dV0 + 32 * 144;

    float m_i[2] = {-1e30f, -1e30f};
    float l_i[2] = {0.0f, 0.0f};
    float acc[8][4];
    #pragma unroll
    for (int i = 0; i < 8; i++)
        #pragma unroll
        for (int j = 0; j < 4; j++) acc[i][j] = 0.0f;

    const int nkb = (qb0 + QT) / KT;

    {
        const __half* Kg = g_Kh + headbase;
        const __half* Vg = g_Vh + headbase;
        cp16(stBase + dK0, Kg + (size_t)rKs * D_MODEL + c8s * 8);
        cp16(stBase + dK1, Kg + (size_t)(rKs + 32) * D_MODEL + c8s * 8);
        cp16(stBase + dV0, Vg + (size_t)rKs * D_MODEL + c8s * 8);
        cp16(stBase + dV1, Vg + (size_t)(rKs + 32) * D_MODEL + c8s * 8);
        cp_commit();
    }

    for (int kb = 0; kb < nkb; kb++) {
        __syncthreads();

        if (kb + 1 < nkb) {
            const __half* Kg = g_Kh + headbase + (size_t)(kb + 1) * KT * D_MODEL;
            const __half* Vg = g_Vh + headbase + (size_t)(kb + 1) * KT * D_MODEL;
            const uint32_t sb = stBase + ((kb + 1) & 1) * KV_STG_B;
            cp16(sb + dK0, Kg + (size_t)rKs * D_MODEL + c8s * 8);
            cp16(sb + dK1, Kg + (size_t)(rKs + 32) * D_MODEL + c8s * 8);
            cp16(sb + dV0, Vg + (size_t)rKs * D_MODEL + c8s * 8);
            cp16(sb + dV1, Vg + (size_t)(rKs + 32) * D_MODEL + c8s * 8);
            cp_commit();
            cp_wait1();
        } else {
            cp_wait0();
        }
        __syncthreads();

        const uint32_t kLane = stBase + (kb & 1) * KV_STG_B + laneOfs;
        const uint32_t vLane = kLane + KT * PADW * 4;
        const int kb64 = kb * KT;

        // ---- S (log2 domain) : skip warp-uniform fully-masked blocks ----
        float s[8][4];
        #pragma unroll
        for (int i = 0; i < 8; i++)
            #pragma unroll
            for (int j = 0; j < 4; j++) s[i][j] = 0.0f;

        #pragma unroll
        for (int ks = 0; ks < 4; ks++) {
            const uint32_t kByte = ks * 32;
            uint32_t a[4];
            ldsm4(a[0], a[1], a[2], a[3], qLane + kByte);
            #pragma unroll
            for (int j = 0; j < 4; j++) {
                if (kb64 + j * 16 <= rowMax) {        // block touches causal region
                    uint32_t m0, m1, m2, m3;
                    ldsm4(m0, m1, m2, m3, kLane + kByte + (((j * 16) * PADW) << 2));
                    uint32_t b0[2] = {m0, m2}, b1[2] = {m1, m3};
                    mma_f16(s[2 * j], a, b0);
                    if (kb64 + j * 16 + 8 <= rowMax)
                        mma_f16(s[2 * j + 1], a, b1);
                }
            }
        }

        // ---- causal mask ----
        const int r0g = qb0 + row0 + g;
        if ((kb + 1) * KT - 1 > qb0 + row0) {
            #pragma unroll
            for (int nt = 0; nt < 8; nt++) {
                int c = kb64 + nt * 8 + 2 * t;
                if (c     > r0g)     s[nt][0] = -1e30f;
                if (c + 1 > r0g)     s[nt][1] = -1e30f;
                if (c     > r0g + 8) s[nt][2] = -1e30f;
                if (c + 1 > r0g + 8) s[nt][3] = -1e30f;
            }
        }

        // ---- online softmax, log2 domain ----
        float mx0 = -1e30f, mx1 = -1e30f;
        #pragma unroll
        for (int nt = 0; nt < 8; nt++) {
            mx0 = fmaxf(mx0, fmaxf(s[nt][0], s[nt][1]));
            mx1 = fmaxf(mx1, fmaxf(s[nt][2], s[nt][3]));
        }
        mx0 = fmaxf(mx0, __shfl_xor_sync(0xFFFFFFFFu, mx0, 1));
        mx0 = fmaxf(mx0, __shfl_xor_sync(0xFFFFFFFFu, mx0, 2));
        mx1 = fmaxf(mx1, __shfl_xor_sync(0xFFFFFFFFu, mx1, 1));
        mx1 = fmaxf(mx1, __shfl_xor_sync(0xFFFFFFFFu, mx1, 2));

        const float mn0 = fmaxf(m_i[0], mx0);
        const float mn1 = fmaxf(m_i[1], mx1);
        const float co0 = ex2(m_i[0] - mn0);
        const float co1 = ex2(m_i[1] - mn1);
        m_i[0] = mn0; m_i[1] = mn1;

        float rs0 = 0.0f, rs1 = 0.0f;
        #pragma unroll
        for (int nt = 0; nt < 8; nt++) {
            s[nt][0] = ex2(s[nt][0] - mn0);
            s[nt][1] = ex2(s[nt][1] - mn0);
            s[nt][2] = ex2(s[nt][2] - mn1);
            s[nt][3] = ex2(s[nt][3] - mn1);
            rs0 += s[nt][0] + s[nt][1];
            rs1 += s[nt][2] + s[nt][3];
        }
        rs0 += __shfl_xor_sync(0xFFFFFFFFu, rs0, 1);
        rs0 += __shfl_xor_sync(0xFFFFFFFFu, rs0, 2);
        rs1 += __shfl_xor_sync(0xFFFFFFFFu, rs1, 1);
        rs1 += __shfl_xor_sync(0xFFFFFFFFu, rs1, 2);
        l_i[0] = l_i[0] * co0 + rs0;
        l_i[1] = l_i[1] * co1 + rs1;

        #pragma unroll
        for (int nt = 0; nt < 8; nt++) {
            acc[nt][0] *= co0; acc[nt][1] *= co0;
            acc[nt][2] *= co1; acc[nt][3] *= co1;
        }

        // ---- acc += P V : skip fully-masked k-steps (P there is exactly 0)
        #pragma unroll
        for (int ks = 0; ks < 4; ks++) {
            if (kb64 + ks * 16 > rowMax) continue;    // warp-uniform
            uint32_t a[4] = {
                f2h2(s[2 * ks][0],     s[2 * ks][1]),
                f2h2(s[2 * ks][2],     s[2 * ks][3]),
                f2h2(s[2 * ks + 1][0], s[2 * ks + 1][1]),
                f2h2(s[2 * ks + 1][2], s[2 * ks + 1][3])
            };
            const uint32_t vRow = vLane + ((ks * 16 * PADW) << 2);
            #pragma unroll
            for (int j = 0; j < 4; j++) {
                uint32_t m0, m1, m2, m3;
                ldsm4t(m0, m1, m2, m3, vRow + j * 32);
                uint32_t b0[2] = {m0, m1}, b1[2] = {m2, m3};
                mma_f16(acc[2 * j],     a, b0);
                mma_f16(acc[2 * j + 1], a, b1);
            }
        }
    }

    // ---- epilogue: normalize, write AO as fp16 ----
    const float inv0 = 1.0f / l_i[0];
    const float inv1 = 1.0f / l_i[1];
    uint32_t* AO = (uint32_t*)g_AOh;
    const size_t w0 = (headbase + (size_t)(qb0 + row0 + g) * D_MODEL) >> 1;
    const size_t w1 = w0 + 4 * D_MODEL;
    #pragma unroll
    for (int nt = 0; nt < 8; nt++) {
        const int c = nt * 8 + 2 * t;
        AO[w0 + (c >> 1)] = f2h2(acc[nt][0] * inv0, acc[nt][1] * inv0);
        AO[w1 + (c >> 1)] = f2h2(acc[nt][2] * inv1, acc[nt][3] * inv1);
    }
}

// ---------------------------------------------------------------------------
// Launch
// ---------------------------------------------------------------------------
extern "C" void kernel_launch(void* const* d_in, const int* in_sizes, int n_in,
                              void* d_out, int out_size)
{
    const float* X  = (const float*)d_in[0];
    const float* Wq = (const float*)d_in[1];
    const float* bq = (const float*)d_in[2];
    const float* Wk = (const float*)d_in[3];
    const float* bk = (const float*)d_in[4];
    const float* Wv = (const float*)d_in[5];
    const float* bv = (const float*)d_in[6];
    const float* Wo = (const float*)d_in[7];
    const float* bo = (const float*)d_in[8];
    float* out = (float*)d_out;

    cudaFuncSetAttribute(gemm_qkv, cudaFuncAttributeMaxDynamicSharedMemorySize,
                         GEMM_SMEM_BYTES);
    cudaFuncSetAttribute(gemm_out, cudaFuncAttributeMaxDynamicSharedMemorySize,
                         GEMM_SMEM_BYTES);
    cudaFuncSetAttribute(attn_mma, cudaFuncAttributeMaxDynamicSharedMemorySize,
                         ATTN_SMEM_BYTES);

    convert_fp16<<<dim3(512, 1, 5), 256>>>(X, Wq, Wk, Wv, Wo);

    dim3 qkv_grid(D_MODEL / 128, NTOK / 128, 3);  // (8, 32, 3)
    dim3 out_grid(D_MODEL / 128, NTOK / 128);     // (8, 32)

    gemm_qkv<<<qkv_grid, 256, GEMM_SMEM_BYTES>>>(bq, bk, bv);

    attn_mma<<<dim3(S_LEN / QT, NH, NBATCH), 256, ATTN_SMEM_BYTES>>>();

    gemm_out<<<out_grid, 256, GEMM_SMEM_BYTES>>>(bo, out);
}

// round 16
// speedup vs baseline: 1.0380x; 1.0380x over previous
#include <cuda_runtime.h>
#include <cuda_fp16.h>
#include <cstdint>

// Problem constants
#define D_MODEL 1024
#define S_LEN   2048
#define NH      16
#define HDIM    64
#define NBATCH  2
#define NTOK    (NBATCH * S_LEN)   // 4096
#define DD      (D_MODEL * D_MODEL)

// Scratch (static __device__ globals — allocation-free per harness rules)
__device__ __half g_Xh [NTOK * D_MODEL];
__device__ __half g_Wh [4 * DD];            // Wq, Wk, Wv, Wo (fp16)
__device__ __half g_Qh [NTOK * D_MODEL];    // pre-scaled by log2e/8
__device__ __half g_Kh [NTOK * D_MODEL];
__device__ __half g_Vh [NTOK * D_MODEL];
__device__ __half g_AOh[NTOK * D_MODEL];

// ---------------------------------------------------------------------------
// Helpers (legacy tensor-core path — tcgen05 rejected by sm_100 PTX target).
// R16 = R15 minus the attention mma-skip branches (measured −10us regression:
// predication broke ptxas scheduling of the unrolled ldsm/mma stream).
// 4-stage GEMM pipeline and log2-domain softmax retained (measured/neutral).
// ---------------------------------------------------------------------------
__device__ __forceinline__ uint32_t f2h2(float lo, float hi) {
    __half2 h = __floats2half2_rn(lo, hi);
    return *(uint32_t*)&h;
}
__device__ __forceinline__ uint32_t smem_addr_u32(const void* p) {
    return (uint32_t)__cvta_generic_to_shared(p);
}
__device__ __forceinline__ float ex2(float x) {
    float y; asm("ex2.approx.f32 %0, %1;" : "=f"(y) : "f"(x)); return y;
}
__device__ __forceinline__ void mma_f16(float* d, const uint32_t* a, const uint32_t* b) {
    asm volatile(
        "mma.sync.aligned.m16n8k16.row.col.f32.f16.f16.f32 "
        "{%0,%1,%2,%3}, {%4,%5,%6,%7}, {%8,%9}, {%0,%1,%2,%3};"
        : "+f"(d[0]), "+f"(d[1]), "+f"(d[2]), "+f"(d[3])
        : "r"(a[0]), "r"(a[1]), "r"(a[2]), "r"(a[3]), "r"(b[0]), "r"(b[1]));
}
__device__ __forceinline__ void ldsm4(uint32_t& r0, uint32_t& r1,
                                      uint32_t& r2, uint32_t& r3, uint32_t addr) {
    asm volatile("ldmatrix.sync.aligned.m8n8.x4.shared.b16 {%0,%1,%2,%3}, [%4];"
                 : "=r"(r0), "=r"(r1), "=r"(r2), "=r"(r3) : "r"(addr));
}
__device__ __forceinline__ void ldsm4t(uint32_t& r0, uint32_t& r1,
                                       uint32_t& r2, uint32_t& r3, uint32_t addr) {
    asm volatile("ldmatrix.sync.aligned.m8n8.x4.trans.shared.b16 {%0,%1,%2,%3}, [%4];"
                 : "=r"(r0), "=r"(r1), "=r"(r2), "=r"(r3) : "r"(addr));
}
__device__ __forceinline__ void cp16(uint32_t dst, const void* src) {
    asm volatile("cp.async.cg.shared.global [%0], [%1], 16;" :: "r"(dst), "l"(src));
}
__device__ __forceinline__ void cp_commit() {
    asm volatile("cp.async.commit_group;" ::: "memory");
}
__device__ __forceinline__ void cp_wait2() {
    asm volatile("cp.async.wait_group 2;" ::: "memory");
}
__device__ __forceinline__ void cp_wait1() {
    asm volatile("cp.async.wait_group 1;" ::: "memory");
}
__device__ __forceinline__ void cp_wait0() {
    asm volatile("cp.async.wait_group 0;" ::: "memory");
}

// ===========================================================================
// fp32 -> fp16 conversion (X + 4 weight matrices).
// ===========================================================================
__global__ void convert_fp16(const float* __restrict__ X,
                             const float* __restrict__ Wq, const float* __restrict__ Wk,
                             const float* __restrict__ Wv, const float* __restrict__ Wo)
{
    const float* src; __half* dst; uint32_t n4;
    switch (blockIdx.z) {
        case 0:  src = X;  dst = g_Xh;          n4 = NTOK * D_MODEL / 4; break;
        case 1:  src = Wq; dst = g_Wh;          n4 = DD / 4; break;
        case 2:  src = Wk; dst = g_Wh + DD;     n4 = DD / 4; break;
        case 3:  src = Wv; dst = g_Wh + 2 * DD; n4 = DD / 4; break;
        default: src = Wo; dst = g_Wh + 3 * DD; n4 = DD / 4; break;
    }
    for (uint32_t i = blockIdx.x * blockDim.x + threadIdx.x; i < n4;
         i += gridDim.x * blockDim.x) {
        float4 v = ((const float4*)src)[i];
        uint2 w = {f2h2(v.x, v.y), f2h2(v.z, v.w)};
        ((uint2*)dst)[i] = w;
    }
}

// ===========================================================================
// fp16 tensor-core GEMM with cp.async 4-stage pipeline (unchanged from R15).
// ===========================================================================
#define ROWB 80
#define STG_BYTES (256 * ROWB)
#define GEMM_SMEM_BYTES (4 * STG_BYTES)         // 81920 B

template <bool HALF_OUT, typename OutT>
__device__ __forceinline__ void gemm_body(
    const __half* __restrict__ A, const __half* __restrict__ B,
    const float* __restrict__ bias, OutT* __restrict__ C,
    int bM, int bN, float scale, void* smv)
{
    const int tid  = threadIdx.x;
    const int lane = tid & 31;
    const int wid  = tid >> 5;
    const int g    = lane >> 2;
    const int t    = lane & 3;
    const int wm   = (wid >> 2) * 64;
    const int wn   = (wid & 3) * 32;

    const uint32_t smu = smem_addr_u32(smv);
    const uint32_t aLane = smu + (lane & 15) * ROWB + ((lane >> 4) << 4);
    const uint32_t bLane = aLane + 128 * ROWB;

    const int ch = tid & 3;
    const int rr = tid >> 2;
    const __half* sA0 = A + (size_t)(bM + rr) * D_MODEL + ch * 8;
    const __half* sA1 = sA0 + (size_t)64 * D_MODEL;
    const __half* sB0 = B + (size_t)(bN + rr) * D_MODEL + ch * 8;
    const __half* sB1 = sB0 + (size_t)64 * D_MODEL;
    const uint32_t dA0 = rr * ROWB + ch * 16;
    const uint32_t dA1 = dA0 + 64 * ROWB;
    const uint32_t dB0 = dA0 + 128 * ROWB;
    const uint32_t dB1 = dB0 + 64 * ROWB;

    float acc[16][4];
    #pragma unroll
    for (int i = 0; i < 16; i++)
        #pragma unroll
        for (int j = 0; j < 4; j++) acc[i][j] = 0.0f;

    #pragma unroll
    for (int s = 0; s < 3; s++) {
        const uint32_t sb = smu + s * STG_BYTES;
        const int kt = s * 32;
        cp16(sb + dA0, sA0 + kt);
        cp16(sb + dA1, sA1 + kt);
        cp16(sb + dB0, sB0 + kt);
        cp16(sb + dB1, sB1 + kt);
        cp_commit();
    }

    for (int s = 0; s < 32; s++) {
        if (s < 30) cp_wait2(); else cp_wait0();
        __syncthreads();

        if (s + 3 < 32) {
            const uint32_t sb = smu + ((s + 3) & 3) * STG_BYTES;
            const int kt = (s + 3) * 32;
            cp16(sb + dA0, sA0 + kt);
            cp16(sb + dA1, sA1 + kt);
            cp16(sb + dB0, sB0 + kt);
            cp16(sb + dB1, sB1 + kt);
            cp_commit();
        }

        const uint32_t bufByte = (uint32_t)(s & 3) * STG_BYTES;
        #pragma unroll
        for (int ks = 0; ks < 2; ks++) {
            const uint32_t kByte = bufByte + ks * 32;
            uint32_t af[4][4];
            #pragma unroll
            for (int i = 0; i < 4; i++)
                ldsm4(af[i][0], af[i][1], af[i][2], af[i][3],
                      aLane + kByte + (wm + i * 16) * ROWB);
            #pragma unroll
            for (int j = 0; j < 2; j++) {
                uint32_t m0, m1, m2, m3;
                ldsm4(m0, m1, m2, m3, bLane + kByte + (wn + j * 16) * ROWB);
                uint32_t b0[2] = {m0, m2}, b1[2] = {m1, m3};
                #pragma unroll
                for (int i = 0; i < 4; i++) {
                    mma_f16(acc[i * 4 + 2 * j],     af[i], b0);
                    mma_f16(acc[i * 4 + 2 * j + 1], af[i], b1);
                }
            }
        }
    }

    #pragma unroll
    for (int i = 0; i < 4; i++) {
        const int m0 = bM + wm + i * 16 + g;
        #pragma unroll
        for (int j = 0; j < 4; j++) {
            const int col = bN + wn + j * 8 + 2 * t;
            float2 bb = *(const float2*)(bias + col);
            float v00 = (acc[i * 4 + j][0] + bb.x) * scale;
            float v01 = (acc[i * 4 + j][1] + bb.y) * scale;
            float v10 = (acc[i * 4 + j][2] + bb.x) * scale;
            float v11 = (acc[i * 4 + j][3] + bb.y) * scale;
            if (HALF_OUT) {
                uint32_t* o = (uint32_t*)C;
                o[((size_t)m0 * D_MODEL + col) >> 1]       = f2h2(v00, v01);
                o[((size_t)(m0 + 8) * D_MODEL + col) >> 1] = f2h2(v10, v11);
            } else {
                float* o = (float*)C;
                *(float2*)(o + (size_t)m0 * D_MODEL + col)       = make_float2(v00, v01);
                *(float2*)(o + (size_t)(m0 + 8) * D_MODEL + col) = make_float2(v10, v11);
            }
        }
    }
}

// Fused QKV. Q is pre-scaled by log2e/8 so softmax runs in log2 domain.
#define QSCALE (0.125f * 1.44269504f)

__global__ __launch_bounds__(256, 2)
void gemm_qkv(const float* __restrict__ bq, const float* __restrict__ bk,
              const float* __restrict__ bv)
{
    extern __shared__ char smg[];
    const __half* B; const float* bias; __half* C; float scale;
    if (blockIdx.z == 0)      { B = g_Wh;          bias = bq; C = g_Qh; scale = QSCALE; }
    else if (blockIdx.z == 1) { B = g_Wh + DD;     bias = bk; C = g_Kh; scale = 1.0f; }
    else                      { B = g_Wh + 2 * DD; bias = bv; C = g_Vh; scale = 1.0f; }
    gemm_body<true>(g_Xh, B, bias, C, blockIdx.y * 128, blockIdx.x * 128, scale, smg);
}

__global__ __launch_bounds__(256, 2)
void gemm_out(const float* __restrict__ bo, float* __restrict__ out)
{
    extern __shared__ char smg[];
    gemm_body<false>(g_AOh, g_Wh + 3 * DD, bo, out,
                     blockIdx.y * 128, blockIdx.x * 128, 1.0f, smg);
}

// ===========================================================================
// fp16 causal flash attention (R14 straight-line structure + log2 softmax):
//  - P in registers; V via ldmatrix.trans; cp.async double-buffered K/V
//  - NO branches inside the unrolled mma loops
// ===========================================================================
#define QT 128
#define KT 64
#define PADW 36
#define KV_STG_B (2 * KT * PADW * 4)                    // 18432 B per stage
#define ATTN_SMEM_BYTES (QT * PADW * 4 + 2 * KV_STG_B)  // 55296 B

__global__ __launch_bounds__(256, 2)
void attn_mma()
{
    extern __shared__ uint32_t sma[];
    uint32_t* Qs = sma;
    uint32_t* St = sma + QT * PADW;

    const int tid  = threadIdx.x;
    const int lane = tid & 31;
    const int wid  = tid >> 5;
    const int g    = lane >> 2;
    const int t    = lane & 3;
    const int qt   = (int)(gridDim.x - 1) - (int)blockIdx.x;
    const int h    = blockIdx.y;
    const int n    = blockIdx.z;
    const int qb0  = qt * QT;
    const int row0 = wid * 16;

    const uint32_t laneOfs = (((lane & 15) * PADW + ((lane >> 4) << 2)) << 2);
    const uint32_t qLane  = smem_addr_u32(Qs) + laneOfs + ((row0 * PADW) << 2);
    const uint32_t stBase = smem_addr_u32(St);

    const size_t headbase = ((size_t)n * S_LEN) * D_MODEL + h * HDIM;

    {
        const __half* Qg = g_Qh + headbase + (size_t)qb0 * D_MODEL;
        #pragma unroll
        for (int i = 0; i < 4; i++) {
            int idx = tid + i * 256;
            int r = idx >> 3, c8 = idx & 7;
            uint4 v = *(const uint4*)(Qg + (size_t)r * D_MODEL + c8 * 8);
            *(uint4*)(Qs + r * PADW + c8 * 4) = v;
        }
    }

    const int c8s = tid & 7;
    const int rKs = tid >> 3;
    const uint32_t dK0 = rKs * 144 + c8s * 16;
    const uint32_t dK1 = dK0 + 32 * 144;
    const uint32_t dV0 = dK0 + KT * 144;
    const uint32_t dV1 = dV0 + 32 * 144;

    float m_i[2] = {-1e30f, -1e30f};
    float l_i[2] = {0.0f, 0.0f};
    float acc[8][4];
    #pragma unroll
    for (int i = 0; i < 8; i++)
        #pragma unroll
        for (int j = 0; j < 4; j++) acc[i][j] = 0.0f;

    const int nkb = (qb0 + QT) / KT;

    {
        const __half* Kg = g_Kh + headbase;
        const __half* Vg = g_Vh + headbase;
        cp16(stBase + dK0, Kg + (size_t)rKs * D_MODEL + c8s * 8);
        cp16(stBase + dK1, Kg + (size_t)(rKs + 32) * D_MODEL + c8s * 8);
        cp16(stBase + dV0, Vg + (size_t)rKs * D_MODEL + c8s * 8);
        cp16(stBase + dV1, Vg + (size_t)(rKs + 32) * D_MODEL + c8s * 8);
        cp_commit();
    }

    for (int kb = 0; kb < nkb; kb++) {
        __syncthreads();

        if (kb + 1 < nkb) {
            const __half* Kg = g_Kh + headbase + (size_t)(kb + 1) * KT * D_MODEL;
            const __half* Vg = g_Vh + headbase + (size_t)(kb + 1) * KT * D_MODEL;
            const uint32_t sb = stBase + ((kb + 1) & 1) * KV_STG_B;
            cp16(sb + dK0, Kg + (size_t)rKs * D_MODEL + c8s * 8);
            cp16(sb + dK1, Kg + (size_t)(rKs + 32) * D_MODEL + c8s * 8);
            cp16(sb + dV0, Vg + (size_t)rKs * D_MODEL + c8s * 8);
            cp16(sb + dV1, Vg + (size_t)(rKs + 32) * D_MODEL + c8s * 8);
            cp_commit();
            cp_wait1();
        } else {
            cp_wait0();
        }
        __syncthreads();

        const uint32_t kLane = stBase + (kb & 1) * KV_STG_B + laneOfs;
        const uint32_t vLane = kLane + KT * PADW * 4;

        // ---- S (log2 domain) : 4 k16-steps x 8 n-tiles, straight-line ----
        float s[8][4];
        #pragma unroll
        for (int i = 0; i < 8; i++)
            #pragma unroll
            for (int j = 0; j < 4; j++) s[i][j] = 0.0f;

        #pragma unroll
        for (int ks = 0; ks < 4; ks++) {
            const uint32_t kByte = ks * 32;
            uint32_t a[4];
            ldsm4(a[0], a[1], a[2], a[3], qLane + kByte);
            #pragma unroll
            for (int j = 0; j < 4; j++) {
                uint32_t m0, m1, m2, m3;
                ldsm4(m0, m1, m2, m3, kLane + kByte + (((j * 16) * PADW) << 2));
                uint32_t b0[2] = {m0, m2}, b1[2] = {m1, m3};
                mma_f16(s[2 * j],     a, b0);
                mma_f16(s[2 * j + 1], a, b1);
            }
        }

        // ---- causal mask ----
        const int r0g = qb0 + row0 + g;
        if ((kb + 1) * KT - 1 > qb0 + row0) {
            #pragma unroll
            for (int nt = 0; nt < 8; nt++) {
                int c = kb * KT + nt * 8 + 2 * t;
                if (c     > r0g)     s[nt][0] = -1e30f;
                if (c + 1 > r0g)     s[nt][1] = -1e30f;
                if (c     > r0g + 8) s[nt][2] = -1e30f;
                if (c + 1 > r0g + 8) s[nt][3] = -1e30f;
            }
        }

        // ---- online softmax, log2 domain ----
        float mx0 = -1e30f, mx1 = -1e30f;
        #pragma unroll
        for (int nt = 0; nt < 8; nt++) {
            mx0 = fmaxf(mx0, fmaxf(s[nt][0], s[nt][1]));
            mx1 = fmaxf(mx1, fmaxf(s[nt][2], s[nt][3]));
        }
        mx0 = fmaxf(mx0, __shfl_xor_sync(0xFFFFFFFFu, mx0, 1));
        mx0 = fmaxf(mx0, __shfl_xor_sync(0xFFFFFFFFu, mx0, 2));
        mx1 = fmaxf(mx1, __shfl_xor_sync(0xFFFFFFFFu, mx1, 1));
        mx1 = fmaxf(mx1, __shfl_xor_sync(0xFFFFFFFFu, mx1, 2));

        const float mn0 = fmaxf(m_i[0], mx0);
        const float mn1 = fmaxf(m_i[1], mx1);
        const float co0 = ex2(m_i[0] - mn0);
        const float co1 = ex2(m_i[1] - mn1);
        m_i[0] = mn0; m_i[1] = mn1;

        float rs0 = 0.0f, rs1 = 0.0f;
        #pragma unroll
        for (int nt = 0; nt < 8; nt++) {
            s[nt][0] = ex2(s[nt][0] - mn0);
            s[nt][1] = ex2(s[nt][1] - mn0);
            s[nt][2] = ex2(s[nt][2] - mn1);
            s[nt][3] = ex2(s[nt][3] - mn1);
            rs0 += s[nt][0] + s[nt][1];
            rs1 += s[nt][2] + s[nt][3];
        }
        rs0 += __shfl_xor_sync(0xFFFFFFFFu, rs0, 1);
        rs0 += __shfl_xor_sync(0xFFFFFFFFu, rs0, 2);
        rs1 += __shfl_xor_sync(0xFFFFFFFFu, rs1, 1);
        rs1 += __shfl_xor_sync(0xFFFFFFFFu, rs1, 2);
        l_i[0] = l_i[0] * co0 + rs0;
        l_i[1] = l_i[1] * co1 + rs1;

        #pragma unroll
        for (int nt = 0; nt < 8; nt++) {
            acc[nt][0] *= co0; acc[nt][1] *= co0;
            acc[nt][2] *= co1; acc[nt][3] *= co1;
        }

        // ---- acc += P V : straight-line, P from registers, V via trans ----
        #pragma unroll
        for (int ks = 0; ks < 4; ks++) {
            uint32_t a[4] = {
                f2h2(s[2 * ks][0],     s[2 * ks][1]),
                f2h2(s[2 * ks][2],     s[2 * ks][3]),
                f2h2(s[2 * ks + 1][0], s[2 * ks + 1][1]),
                f2h2(s[2 * ks + 1][2], s[2 * ks + 1][3])
            };
            const uint32_t vRow = vLane + ((ks * 16 * PADW) << 2);
            #pragma unroll
            for (int j = 0; j < 4; j++) {
                uint32_t m0, m1, m2, m3;
                ldsm4t(m0, m1, m2, m3, vRow + j * 32);
                uint32_t b0[2] = {m0, m1}, b1[2] = {m2, m3};
                mma_f16(acc[2 * j],     a, b0);
                mma_f16(acc[2 * j + 1], a, b1);
            }
        }
    }

    // ---- epilogue: normalize, write AO as fp16 ----
    const float inv0 = 1.0f / l_i[0];
    const float inv1 = 1.0f / l_i[1];
    uint32_t* AO = (uint32_t*)g_AOh;
    const size_t w0 = (headbase + (size_t)(qb0 + row0 + g) * D_MODEL) >> 1;
    const size_t w1 = w0 + 4 * D_MODEL;
    #pragma unroll
    for (int nt = 0; nt < 8; nt++) {
        const int c = nt * 8 + 2 * t;
        AO[w0 + (c >> 1)] = f2h2(acc[nt][0] * inv0, acc[nt][1] * inv0);
        AO[w1 + (c >> 1)] = f2h2(acc[nt][2] * inv1, acc[nt][3] * inv1);
    }
}

// ---------------------------------------------------------------------------
// Launch
// ---------------------------------------------------------------------------
extern "C" void kernel_launch(void* const* d_in, const int* in_sizes, int n_in,
                              void* d_out, int out_size)
{
    const float* X  = (const float*)d_in[0];
    const float* Wq = (const float*)d_in[1];
    const float* bq = (const float*)d_in[2];
    const float* Wk = (const float*)d_in[3];
    const float* bk = (const float*)d_in[4];
    const float* Wv = (const float*)d_in[5];
    const float* bv = (const float*)d_in[6];
    const float* Wo = (const float*)d_in[7];
    const float* bo = (const float*)d_in[8];
    float* out = (float*)d_out;

    cudaFuncSetAttribute(gemm_qkv, cudaFuncAttributeMaxDynamicSharedMemorySize,
                         GEMM_SMEM_BYTES);
    cudaFuncSetAttribute(gemm_out, cudaFuncAttributeMaxDynamicSharedMemorySize,
                         GEMM_SMEM_BYTES);
    cudaFuncSetAttribute(attn_mma, cudaFuncAttributeMaxDynamicSharedMemorySize,
                         ATTN_SMEM_BYTES);

    convert_fp16<<<dim3(512, 1, 5), 256>>>(X, Wq, Wk, Wv, Wo);

    dim3 qkv_grid(D_MODEL / 128, NTOK / 128, 3);  // (8, 32, 3)
    dim3 out_grid(D_MODEL / 128, NTOK / 128);     // (8, 32)

    gemm_qkv<<<qkv_grid, 256, GEMM_SMEM_BYTES>>>(bq, bk, bv);

    attn_mma<<<dim3(S_LEN / QT, NH, NBATCH), 256, ATTN_SMEM_BYTES>>>();

    gemm_out<<<out_grid, 256, GEMM_SMEM_BYTES>>>(bo, out);
}